// round 16
// baseline (speedup 1.0000x reference)
#include <cuda_runtime.h>
#include <cuda_fp16.h>
#include <cstdint>
#include <math.h>

#define T_TOK 1024
#define H_DIM 2048
#define E_NUM 64
#define I_DIM 512
#define IS_DIM 1024
#define TOPK 8
#define CAP 256

#define BKx 32
#define ASTRH 24            // half2 per A row (16 data, permuted, + 8 pad) -> LDS.64 conflict-free
#define BSTRH_D 72          // half2 per B k2-row (dual, 64 data + 8 pad)
#define BSTRH_S 136         // half2 per B k2-row (single, 128 data + 8 pad)
#define A_STG (128 * ASTRH)             // 3072 u32
#define BD_STG (16 * BSTRH_D)           // 1152 u32
#define BS_STG (16 * BSTRH_S)           // 2176 u32
#define SMEM_DUAL ((2 * A_STG + 2 * 2 * BD_STG) * 4)   // 43008 B
#define SMEM_SINGLE ((2 * A_STG + 2 * BS_STG) * 4)     // 41984 B

// ---------------- scratch (static device globals; no allocs) ----------------
__device__ int    d_topk_idx[T_TOK * TOPK];
__device__ float  d_topk_w[T_TOK * TOPK];
__device__ float  d_sgate[T_TOK];
__device__ int    d_cnt[E_NUM];
__device__ int    d_toklist[E_NUM * CAP];
__device__ int    d_pos[T_TOK * TOPK];
__device__ float  d_gbuf[(size_t)E_NUM * CAP * I_DIM];
__device__ float  d_yb[(size_t)E_NUM * CAP * H_DIM];
__device__ float  d_s1[(size_t)T_TOK * IS_DIM];
__device__ float  d_s2[(size_t)T_TOK * H_DIM];

// ---------------- helpers ----------------
__device__ __forceinline__ unsigned pack2(float x, float y) {
    __half2 h = __floats2half2_rn(x, y);   // .x = x (low), .y = y (high)
    return *reinterpret_cast<unsigned*>(&h);
}

// column permutation placing mma pair (k2, k2+4) adjacent
__device__ __forceinline__ int permk(int k2) {
    return (k2 & 8) + ((k2 >> 2) & 1) + 2 * (k2 & 3);
}

__device__ __forceinline__ void mma16(float* c, const unsigned* a, unsigned b0, unsigned b1) {
    asm volatile(
        "mma.sync.aligned.m16n8k16.row.col.f32.f16.f16.f32 "
        "{%0,%1,%2,%3}, {%4,%5,%6,%7}, {%8,%9}, {%0,%1,%2,%3};"
        : "+f"(c[0]), "+f"(c[1]), "+f"(c[2]), "+f"(c[3])
        : "r"(a[0]), "r"(a[1]), "r"(a[2]), "r"(a[3]), "r"(b0), "r"(b1));
}

// ---------------- router v2: 8 tokens/block, gw read once per block ----------------
// Block 0 also zeroes the dispatch counters (router completes before dispatch launches).
__global__ void __launch_bounds__(256)
router_kernel(const float* __restrict__ x,
              const float* __restrict__ gw,
              const float* __restrict__ wsg) {
    __shared__ float part[8][8 * 65];
    __shared__ float logits[8 * 65];

    int tid = threadIdx.x, w = tid >> 5, lane = tid & 31;
    int t0 = blockIdx.x * 8;

    if (blockIdx.x == 0 && tid < E_NUM) d_cnt[tid] = 0;

    float4 xr[8][2];
    #pragma unroll
    for (int t = 0; t < 8; t++) {
        const float4* xrow = (const float4*)(x + (size_t)(t0 + t) * H_DIM);
        #pragma unroll
        for (int j = 0; j < 2; j++)
            xr[t][j] = xrow[w * 64 + j * 32 + lane];
    }

    for (int e = 0; e < E_NUM + 1; e++) {
        const float4* wrow = (const float4*)((e < E_NUM) ? (gw + (size_t)e * H_DIM) : wsg);
        float4 wv0 = wrow[w * 64 + lane];
        float4 wv1 = wrow[w * 64 + 32 + lane];
        float acc[8];
        #pragma unroll
        for (int t = 0; t < 8; t++) {
            acc[t] = xr[t][0].x * wv0.x + xr[t][0].y * wv0.y +
                     xr[t][0].z * wv0.z + xr[t][0].w * wv0.w +
                     xr[t][1].x * wv1.x + xr[t][1].y * wv1.y +
                     xr[t][1].z * wv1.z + xr[t][1].w * wv1.w;
        }
        #pragma unroll
        for (int o = 16; o; o >>= 1)
            #pragma unroll
            for (int t = 0; t < 8; t++)
                acc[t] += __shfl_xor_sync(0xffffffffu, acc[t], o);
        if (lane < 8) part[w][lane * 65 + e] = acc[lane];
    }
    __syncthreads();

    for (int idx = tid; idx < 8 * 65; idx += 256) {
        float s = 0.f;
        #pragma unroll
        for (int ww = 0; ww < 8; ww++) s += part[ww][idx];
        logits[idx] = s;
    }
    __syncthreads();

    if (tid < 8) {
        const float* lg = logits + tid * 65;
        int t = t0 + tid;
        unsigned long long used = 0ull;
        float vals[TOPK]; int idx[TOPK];
        for (int k = 0; k < TOPK; k++) {
            float best = -INFINITY; int bi = 0;
            for (int e = 0; e < E_NUM; e++)
                if (!((used >> e) & 1ull) && lg[e] > best) { best = lg[e]; bi = e; }
            used |= 1ull << bi; vals[k] = best; idx[k] = bi;
        }
        float m = vals[0], sum = 0.f, wgt[TOPK];
        for (int k = 0; k < TOPK; k++) { wgt[k] = expf(vals[k] - m); sum += wgt[k]; }
        float inv = 1.f / sum;
        for (int k = 0; k < TOPK; k++) {
            d_topk_w[t * TOPK + k]  = wgt[k] * inv;
            d_topk_idx[t * TOPK + k] = idx[k];
        }
        d_sgate[t] = lg[E_NUM];
    }
}

// ------- dispatch v4: atomic slot assignment (output-invariant permutation) -------
__global__ void __launch_bounds__(1024)
dispatch_kernel() {
    int i = blockIdx.x * 1024 + threadIdx.x;
    int e = d_topk_idx[i];
    int pos = atomicAdd(&d_cnt[e], 1);
    d_pos[i] = pos;
    if (pos < CAP) d_toklist[e * CAP + pos] = i >> 3;
}

// ---------------- dual GEMM fp16 (C1=A@B1, C3=A@B3) + SwiGLU epilogue ----------------
// 256 threads, 8 warps (4m x 2n), block tile 128x64 per mat, warp tile 32x32.
// A smem columns permuted so each mma A-pair is one LDS.64.
__global__ void __launch_bounds__(256, 2)
dual_gemm_silu(const float* __restrict__ A, int lda, size_t strideA,
               const int* __restrict__ gather, const int* __restrict__ cnt_,
               int mfull, int mtiles,
               const float* __restrict__ B1g, const float* __restrict__ B3g,
               int ldb, size_t strideB,
               float* __restrict__ Out, int ldo, size_t strideOut, int K) {
    extern __shared__ unsigned smu[];
    unsigned* As2  = smu;                     // 2 * 3072
    unsigned* B1s2 = smu + 2 * A_STG;         // 2 * 1152
    unsigned* B3s2 = B1s2 + 2 * BD_STG;       // 2 * 1152

    int e = blockIdx.x / mtiles;
    int mt = blockIdx.x - e * mtiles;
    int noff = blockIdx.y * 64;
    int ctot = cnt_ ? min(cnt_[e], CAP) : mfull;
    int nrows = ctot - mt * 128;
    if (nrows <= 0) return;
    int valid = min(128, nrows);

    int tid = threadIdx.x;

    const float* ap[4]; int arow_[4];
    int ap0, ap1;   // permuted column slots for this thread's two half2 columns
    {
        int c4 = (tid & 7) * 4, arow0 = tid >> 3;
        int c2 = (tid & 7) * 2;
        ap0 = permk(c2);
        ap1 = permk(c2 + 1);
        #pragma unroll
        for (int i = 0; i < 4; i++) {
            int r = arow0 + i * 32;
            int rr = min(r, valid - 1);
            long grow = gather ? (long)gather[e * CAP + mt * 128 + rr] : ((long)mt * 128 + rr);
            ap[i] = A + (size_t)e * strideA + (size_t)grow * lda + c4;
            arow_[i] = r * ASTRH;
        }
    }
    const float *b1p, *b3p; int bsoff;
    {
        int k2 = tid >> 4, n4 = (tid & 15) * 4;
        size_t go = (size_t)e * strideB + (size_t)(2 * k2) * ldb + noff + n4;
        b1p = B1g + go; b3p = B3g + go;
        bsoff = k2 * BSTRH_D + n4;
    }

    float c1[2][4][4], c3[2][4][4];
    #pragma unroll
    for (int a = 0; a < 2; a++)
        #pragma unroll
        for (int b = 0; b < 4; b++)
            #pragma unroll
            for (int r = 0; r < 4; r++) { c1[a][b][r] = 0.f; c3[a][b][r] = 0.f; }

    int warp = tid >> 5, lane = tid & 31;
    int wm = warp & 3, wn = warp >> 2;
    int g = lane >> 2, t4 = lane & 3;

    uint2 raA[4];
    uint4 rb1, rb3;
    auto ldg_all = [&]() {
        #pragma unroll
        for (int i = 0; i < 4; i++) {
            float4 v = *(const float4*)ap[i]; ap[i] += BKx;
            raA[i] = make_uint2(pack2(v.x, v.y), pack2(v.z, v.w));
        }
        float4 lo1 = *(const float4*)b1p, hi1 = *(const float4*)(b1p + ldb);
        b1p += (size_t)BKx * ldb;
        rb1 = make_uint4(pack2(lo1.x, hi1.x), pack2(lo1.y, hi1.y),
                         pack2(lo1.z, hi1.z), pack2(lo1.w, hi1.w));
        float4 lo3 = *(const float4*)b3p, hi3 = *(const float4*)(b3p + ldb);
        b3p += (size_t)BKx * ldb;
        rb3 = make_uint4(pack2(lo3.x, hi3.x), pack2(lo3.y, hi3.y),
                         pack2(lo3.z, hi3.z), pack2(lo3.w, hi3.w));
    };
    auto sts_all = [&](int s) {
        unsigned* as = As2 + s * A_STG;
        #pragma unroll
        for (int i = 0; i < 4; i++) {
            as[arow_[i] + ap0] = raA[i].x;
            as[arow_[i] + ap1] = raA[i].y;
        }
        *(uint4*)&B1s2[s * BD_STG + bsoff] = rb1;
        *(uint4*)&B3s2[s * BD_STG + bsoff] = rb3;
    };

    int nk = K / BKx;
    ldg_all();
    for (int i = 0; i < nk; i++) {
        int s = i & 1;
        sts_all(s);
        __syncthreads();
        if (i + 1 < nk) ldg_all();
        const unsigned* as  = As2 + s * A_STG;
        const unsigned* b1s = B1s2 + s * BD_STG;
        const unsigned* b3s = B3s2 + s * BD_STG;
        #pragma unroll
        for (int kk2 = 0; kk2 < 2; kk2++) {
            int kb = kk2 * 8 + t4;
            int kp = kk2 * 8 + t4 * 2;   // permuted pair base
            unsigned af[2][4];
            #pragma unroll
            for (int mf = 0; mf < 2; mf++) {
                int r0 = wm * 32 + mf * 16 + g;
                uint2 u0 = *(const uint2*)&as[r0 * ASTRH + kp];
                uint2 u1 = *(const uint2*)&as[(r0 + 8) * ASTRH + kp];
                af[mf][0] = u0.x; af[mf][1] = u1.x;
                af[mf][2] = u0.y; af[mf][3] = u1.y;
            }
            unsigned bf1[4][2], bf3[4][2];
            #pragma unroll
            for (int nf = 0; nf < 4; nf++) {
                int cn = wn * 32 + nf * 8 + g;
                bf1[nf][0] = b1s[kb * BSTRH_D + cn];
                bf1[nf][1] = b1s[(kb + 4) * BSTRH_D + cn];
                bf3[nf][0] = b3s[kb * BSTRH_D + cn];
                bf3[nf][1] = b3s[(kb + 4) * BSTRH_D + cn];
            }
            #pragma unroll
            for (int mf = 0; mf < 2; mf++)
                #pragma unroll
                for (int nf = 0; nf < 4; nf++) {
                    mma16(c1[mf][nf], af[mf], bf1[nf][0], bf1[nf][1]);
                    mma16(c3[mf][nf], af[mf], bf3[nf][0], bf3[nf][1]);
                }
        }
        __syncthreads();
    }

    float* outp = Out + (size_t)e * strideOut + (size_t)mt * 128 * ldo + noff;
    #pragma unroll
    for (int mf = 0; mf < 2; mf++)
        #pragma unroll
        for (int nf = 0; nf < 4; nf++) {
            int r0 = wm * 32 + mf * 16 + g;
            int cc = wn * 32 + nf * 8 + t4 * 2;
            #pragma unroll
            for (int h = 0; h < 2; h++) {
                int r = r0 + h * 8;
                if (r < valid) {
                    float v1a = c1[mf][nf][h * 2 + 0], v3a = c3[mf][nf][h * 2 + 0];
                    float v1b = c1[mf][nf][h * 2 + 1], v3b = c3[mf][nf][h * 2 + 1];
                    float ga = (v1a / (1.f + expf(-v1a))) * v3a;
                    float gb = (v1b / (1.f + expf(-v1b))) * v3b;
                    *(float2*)(outp + (size_t)r * ldo + cc) = make_float2(ga, gb);
                }
            }
        }
}

// ---------------- single GEMM fp16 (C = A @ B) ----------------
// 256 threads, 8 warps (4m x 2n), block tile 128x128, warp tile 32x64.
__global__ void __launch_bounds__(256, 2)
single_gemm(const float* __restrict__ A, int lda, size_t strideA,
            const int* __restrict__ cnt_, int mfull, int mtiles,
            const float* __restrict__ Bg, int ldb, size_t strideB,
            float* __restrict__ Out, int ldo, size_t strideOut, int K) {
    extern __shared__ unsigned smu[];
    unsigned* As2 = smu;                  // 2 * 3072
    unsigned* Bs2 = smu + 2 * A_STG;      // 2 * 2176

    int e = blockIdx.x / mtiles;
    int mt = blockIdx.x - e * mtiles;
    int noff = blockIdx.y * 128;
    int ctot = cnt_ ? min(cnt_[e], CAP) : mfull;
    int nrows = ctot - mt * 128;
    if (nrows <= 0) return;
    int valid = min(128, nrows);

    int tid = threadIdx.x;

    const float* ap[4]; int arow_[4];
    int ap0, ap1;
    {
        int c4 = (tid & 7) * 4, arow0 = tid >> 3;
        int c2 = (tid & 7) * 2;
        ap0 = permk(c2);
        ap1 = permk(c2 + 1);
        #pragma unroll
        for (int i = 0; i < 4; i++) {
            int r = arow0 + i * 32;
            int rr = min(r, valid - 1);
            ap[i] = A + (size_t)e * strideA + ((size_t)mt * 128 + rr) * lda + c4;
            arow_[i] = r * ASTRH;
        }
    }
    const float* bp[2]; int bsoff[2];
    #pragma unroll
    for (int j = 0; j < 2; j++) {
        int slot = tid + j * 256;
        int k2 = slot >> 5, n4 = (slot & 31) * 4;
        bp[j] = Bg + (size_t)e * strideB + (size_t)(2 * k2) * ldb + noff + n4;
        bsoff[j] = k2 * BSTRH_S + n4;
    }

    float c[2][8][4];
    #pragma unroll
    for (int a = 0; a < 2; a++)
        #pragma unroll
        for (int b = 0; b < 8; b++)
            #pragma unroll
            for (int r = 0; r < 4; r++) c[a][b][r] = 0.f;

    int warp = tid >> 5, lane = tid & 31;
    int wm = warp & 3, wn = warp >> 2;
    int g = lane >> 2, t4 = lane & 3;

    uint2 raA[4];
    uint4 rbS[2];
    auto ldg_all = [&]() {
        #pragma unroll
        for (int i = 0; i < 4; i++) {
            float4 v = *(const float4*)ap[i]; ap[i] += BKx;
            raA[i] = make_uint2(pack2(v.x, v.y), pack2(v.z, v.w));
        }
        #pragma unroll
        for (int j = 0; j < 2; j++) {
            float4 lo = *(const float4*)bp[j], hi = *(const float4*)(bp[j] + ldb);
            bp[j] += (size_t)BKx * ldb;
            rbS[j] = make_uint4(pack2(lo.x, hi.x), pack2(lo.y, hi.y),
                                pack2(lo.z, hi.z), pack2(lo.w, hi.w));
        }
    };
    auto sts_all = [&](int s) {
        unsigned* as = As2 + s * A_STG;
        #pragma unroll
        for (int i = 0; i < 4; i++) {
            as[arow_[i] + ap0] = raA[i].x;
            as[arow_[i] + ap1] = raA[i].y;
        }
        #pragma unroll
        for (int j = 0; j < 2; j++)
            *(uint4*)&Bs2[s * BS_STG + bsoff[j]] = rbS[j];
    };

    int nk = K / BKx;
    ldg_all();
    for (int i = 0; i < nk; i++) {
        int s = i & 1;
        sts_all(s);
        __syncthreads();
        if (i + 1 < nk) ldg_all();
        const unsigned* as = As2 + s * A_STG;
        const unsigned* bs = Bs2 + s * BS_STG;
        #pragma unroll
        for (int kk2 = 0; kk2 < 2; kk2++) {
            int kb = kk2 * 8 + t4;
            int kp = kk2 * 8 + t4 * 2;
            unsigned af[2][4];
            #pragma unroll
            for (int mf = 0; mf < 2; mf++) {
                int r0 = wm * 32 + mf * 16 + g;
                uint2 u0 = *(const uint2*)&as[r0 * ASTRH + kp];
                uint2 u1 = *(const uint2*)&as[(r0 + 8) * ASTRH + kp];
                af[mf][0] = u0.x; af[mf][1] = u1.x;
                af[mf][2] = u0.y; af[mf][3] = u1.y;
            }
            unsigned bf[8][2];
            #pragma unroll
            for (int nf = 0; nf < 8; nf++) {
                int cn = wn * 64 + nf * 8 + g;
                bf[nf][0] = bs[kb * BSTRH_S + cn];
                bf[nf][1] = bs[(kb + 4) * BSTRH_S + cn];
            }
            #pragma unroll
            for (int mf = 0; mf < 2; mf++)
                #pragma unroll
                for (int nf = 0; nf < 8; nf++)
                    mma16(c[mf][nf], af[mf], bf[nf][0], bf[nf][1]);
        }
        __syncthreads();
    }

    float* outp = Out + (size_t)e * strideOut + (size_t)mt * 128 * ldo + noff;
    #pragma unroll
    for (int mf = 0; mf < 2; mf++)
        #pragma unroll
        for (int nf = 0; nf < 8; nf++) {
            int r0 = wm * 32 + mf * 16 + g;
            int cc = wn * 64 + nf * 8 + t4 * 2;
            #pragma unroll
            for (int h = 0; h < 2; h++) {
                int r = r0 + h * 8;
                if (r < valid)
                    *(float2*)(outp + (size_t)r * ldo + cc) =
                        make_float2(c[mf][nf][h * 2 + 0], c[mf][nf][h * 2 + 1]);
            }
        }
}

// ---------------- combine: routed + sigmoid-gated shared ----------------
__global__ void combine_kernel(float* __restrict__ out) {
    int t = blockIdx.x;
    __shared__ int rows[TOPK];
    __shared__ float ws[TOPK];
    if (threadIdx.x < TOPK) {
        int k = threadIdx.x;
        int ee = d_topk_idx[t * TOPK + k];
        int p  = d_pos[t * TOPK + k];
        rows[k] = (p < CAP) ? (ee * CAP + p) : -1;
        ws[k] = d_topk_w[t * TOPK + k];
    }
    __syncthreads();
    float sg = 1.f / (1.f + expf(-d_sgate[t]));
    #pragma unroll
    for (int j = 0; j < 2; j++) {
        int h = threadIdx.x * 4 + j * 1024;
        float4 acc = *(const float4*)(d_s2 + (size_t)t * H_DIM + h);
        acc.x *= sg; acc.y *= sg; acc.z *= sg; acc.w *= sg;
        #pragma unroll
        for (int k = 0; k < TOPK; k++) {
            int r = rows[k];
            if (r >= 0) {
                float w = ws[k];
                float4 y = *(const float4*)(d_yb + (size_t)r * H_DIM + h);
                acc.x += w * y.x; acc.y += w * y.y; acc.z += w * y.z; acc.w += w * y.w;
            }
        }
        *(float4*)(out + (size_t)t * H_DIM + h) = acc;
    }
}

// ---------------- launch ----------------
extern "C" void kernel_launch(void* const* d_in, const int* in_sizes, int n_in,
                              void* d_out, int out_size) {
    (void)in_sizes; (void)n_in; (void)out_size;
    const float* x   = (const float*)d_in[0];
    const float* gw  = (const float*)d_in[1];
    const float* w1  = (const float*)d_in[2];
    const float* w3  = (const float*)d_in[3];
    const float* w2  = (const float*)d_in[4];
    const float* ws1 = (const float*)d_in[5];
    const float* ws3 = (const float*)d_in[6];
    const float* ws2 = (const float*)d_in[7];
    const float* wsg = (const float*)d_in[8];
    float* out = (float*)d_out;

    static cudaStream_t sB = nullptr;
    static cudaEvent_t evFork = nullptr, evJoin = nullptr;
    if (sB == nullptr) {
        cudaStreamCreateWithFlags(&sB, cudaStreamNonBlocking);
        cudaEventCreateWithFlags(&evFork, cudaEventDisableTiming);
        cudaEventCreateWithFlags(&evJoin, cudaEventDisableTiming);
    }

    cudaFuncSetAttribute(dual_gemm_silu, cudaFuncAttributeMaxDynamicSharedMemorySize, SMEM_DUAL);
    cudaFuncSetAttribute(single_gemm,    cudaFuncAttributeMaxDynamicSharedMemorySize, SMEM_SINGLE);

    float *gbuf, *yb, *s1, *s2;
    int *cnt, *toklist;
    cudaGetSymbolAddress((void**)&gbuf, d_gbuf);
    cudaGetSymbolAddress((void**)&yb, d_yb);
    cudaGetSymbolAddress((void**)&s1, d_s1);
    cudaGetSymbolAddress((void**)&s2, d_s2);
    cudaGetSymbolAddress((void**)&cnt, d_cnt);
    cudaGetSymbolAddress((void**)&toklist, d_toklist);

    // fork: shared-expert chain is independent of router/dispatch/experts
    cudaEventRecord(evFork, 0);
    cudaStreamWaitEvent(sB, evFork, 0);

    // ---- stream B: shared expert chain ----
    dual_gemm_silu<<<dim3(8, IS_DIM / 64), 256, SMEM_DUAL, sB>>>(
        x, H_DIM, 0, nullptr, nullptr, T_TOK, 8,
        ws1, ws3, IS_DIM, 0,
        s1, IS_DIM, 0, H_DIM);
    single_gemm<<<dim3(8, H_DIM / 128), 256, SMEM_SINGLE, sB>>>(
        s1, IS_DIM, 0, nullptr, T_TOK, 8,
        ws2, H_DIM, 0,
        s2, H_DIM, 0, IS_DIM);
    cudaEventRecord(evJoin, sB);

    // ---- default stream: routed expert chain ----
    router_kernel<<<T_TOK / 8, 256>>>(x, gw, wsg);
    dispatch_kernel<<<8, 1024>>>();

    dual_gemm_silu<<<dim3(E_NUM * 2, I_DIM / 64), 256, SMEM_DUAL>>>(
        x, H_DIM, 0, toklist, cnt, 0, 2,
        w1, w3, I_DIM, (size_t)H_DIM * I_DIM,
        gbuf, I_DIM, (size_t)CAP * I_DIM, H_DIM);

    single_gemm<<<dim3(E_NUM * 2, H_DIM / 128), 256, SMEM_SINGLE>>>(
        gbuf, I_DIM, (size_t)CAP * I_DIM, cnt, 0, 2,
        w2, H_DIM, (size_t)I_DIM * H_DIM,
        yb, H_DIM, (size_t)CAP * H_DIM, I_DIM);

    // join: combine needs both chains
    cudaStreamWaitEvent(0, evJoin, 0);
    combine_kernel<<<T_TOK, 256>>>(out);
}

// round 17
// speedup vs baseline: 1.1303x; 1.1303x over previous
#include <cuda_runtime.h>
#include <cuda_fp16.h>
#include <cstdint>
#include <math.h>

#define T_TOK 1024
#define H_DIM 2048
#define E_NUM 64
#define I_DIM 512
#define IS_DIM 1024
#define TOPK 8
#define CAP 256

#define BKx 32
#define ASTRH 20            // half2 per A row (16 data + 4 pad)
#define BSTRH_D 72          // half2 per B k2-row (dual, 64 data + 8 pad)
#define BSTRH_S 136         // half2 per B k2-row (single, 128 data + 8 pad)
#define A_STG (128 * ASTRH)             // 2560 u32
#define BD_STG (16 * BSTRH_D)           // 1152 u32
#define BS_STG (16 * BSTRH_S)           // 2176 u32
#define SMEM_DUAL ((2 * A_STG + 2 * 2 * BD_STG) * 4)   // 38912 B
#define SMEM_SINGLE ((2 * A_STG + 2 * BS_STG) * 4)     // 37888 B

// ---------------- scratch (static device globals; no allocs) ----------------
__device__ int    d_topk_idx[T_TOK * TOPK];
__device__ float  d_topk_w[T_TOK * TOPK];
__device__ float  d_sgate[T_TOK];
__device__ int    d_cnt[E_NUM];
__device__ int    d_toklist[E_NUM * CAP];
__device__ int    d_pos[T_TOK * TOPK];
__device__ float  d_gbuf[(size_t)E_NUM * CAP * I_DIM];
__device__ float  d_yb[(size_t)E_NUM * CAP * H_DIM];
__device__ float  d_s1[(size_t)T_TOK * IS_DIM];
__device__ float  d_s2[(size_t)T_TOK * H_DIM];

// ---------------- helpers ----------------
__device__ __forceinline__ unsigned pack2(float x, float y) {
    __half2 h = __floats2half2_rn(x, y);   // .x = x (low), .y = y (high)
    return *reinterpret_cast<unsigned*>(&h);
}

__device__ __forceinline__ void mma16(float* c, const unsigned* a, unsigned b0, unsigned b1) {
    asm volatile(
        "mma.sync.aligned.m16n8k16.row.col.f32.f16.f16.f32 "
        "{%0,%1,%2,%3}, {%4,%5,%6,%7}, {%8,%9}, {%0,%1,%2,%3};"
        : "+f"(c[0]), "+f"(c[1]), "+f"(c[2]), "+f"(c[3])
        : "r"(a[0]), "r"(a[1]), "r"(a[2]), "r"(a[3]), "r"(b0), "r"(b1));
}

// ---------------- router v2: 8 tokens/block, gw read once per block ----------------
// Block 0 also zeroes the dispatch counters (router completes before dispatch launches).
__global__ void __launch_bounds__(256)
router_kernel(const float* __restrict__ x,
              const float* __restrict__ gw,
              const float* __restrict__ wsg) {
    __shared__ float part[8][8 * 65];
    __shared__ float logits[8 * 65];

    int tid = threadIdx.x, w = tid >> 5, lane = tid & 31;
    int t0 = blockIdx.x * 8;

    if (blockIdx.x == 0 && tid < E_NUM) d_cnt[tid] = 0;

    float4 xr[8][2];
    #pragma unroll
    for (int t = 0; t < 8; t++) {
        const float4* xrow = (const float4*)(x + (size_t)(t0 + t) * H_DIM);
        #pragma unroll
        for (int j = 0; j < 2; j++)
            xr[t][j] = xrow[w * 64 + j * 32 + lane];
    }

    for (int e = 0; e < E_NUM + 1; e++) {
        const float4* wrow = (const float4*)((e < E_NUM) ? (gw + (size_t)e * H_DIM) : wsg);
        float4 wv0 = wrow[w * 64 + lane];
        float4 wv1 = wrow[w * 64 + 32 + lane];
        float acc[8];
        #pragma unroll
        for (int t = 0; t < 8; t++) {
            acc[t] = xr[t][0].x * wv0.x + xr[t][0].y * wv0.y +
                     xr[t][0].z * wv0.z + xr[t][0].w * wv0.w +
                     xr[t][1].x * wv1.x + xr[t][1].y * wv1.y +
                     xr[t][1].z * wv1.z + xr[t][1].w * wv1.w;
        }
        #pragma unroll
        for (int o = 16; o; o >>= 1)
            #pragma unroll
            for (int t = 0; t < 8; t++)
                acc[t] += __shfl_xor_sync(0xffffffffu, acc[t], o);
        if (lane < 8) part[w][lane * 65 + e] = acc[lane];
    }
    __syncthreads();

    for (int idx = tid; idx < 8 * 65; idx += 256) {
        float s = 0.f;
        #pragma unroll
        for (int ww = 0; ww < 8; ww++) s += part[ww][idx];
        logits[idx] = s;
    }
    __syncthreads();

    if (tid < 8) {
        const float* lg = logits + tid * 65;
        int t = t0 + tid;
        unsigned long long used = 0ull;
        float vals[TOPK]; int idx[TOPK];
        for (int k = 0; k < TOPK; k++) {
            float best = -INFINITY; int bi = 0;
            for (int e = 0; e < E_NUM; e++)
                if (!((used >> e) & 1ull) && lg[e] > best) { best = lg[e]; bi = e; }
            used |= 1ull << bi; vals[k] = best; idx[k] = bi;
        }
        float m = vals[0], sum = 0.f, wgt[TOPK];
        for (int k = 0; k < TOPK; k++) { wgt[k] = expf(vals[k] - m); sum += wgt[k]; }
        float inv = 1.f / sum;
        for (int k = 0; k < TOPK; k++) {
            d_topk_w[t * TOPK + k]  = wgt[k] * inv;
            d_topk_idx[t * TOPK + k] = idx[k];
        }
        d_sgate[t] = lg[E_NUM];
    }
}

// ------- dispatch v4: atomic slot assignment (output-invariant permutation) -------
__global__ void __launch_bounds__(1024)
dispatch_kernel() {
    int i = blockIdx.x * 1024 + threadIdx.x;
    int e = d_topk_idx[i];
    int pos = atomicAdd(&d_cnt[e], 1);
    d_pos[i] = pos;
    if (pos < CAP) d_toklist[e * CAP + pos] = i >> 3;
}

// ---------------- dual GEMM fp16 (C1=A@B1, C3=A@B3) + SwiGLU epilogue ----------------
// 256 threads, 8 warps (4m x 2n), block tile 128x64 per mat, warp tile 32x32.
__global__ void __launch_bounds__(256, 2)
dual_gemm_silu(const float* __restrict__ A, int lda, size_t strideA,
               const int* __restrict__ gather, const int* __restrict__ cnt_,
               int mfull, int mtiles,
               const float* __restrict__ B1g, const float* __restrict__ B3g,
               int ldb, size_t strideB,
               float* __restrict__ Out, int ldo, size_t strideOut, int K) {
    extern __shared__ unsigned smu[];
    unsigned* As2  = smu;                     // 2 * 2560
    unsigned* B1s2 = smu + 2 * A_STG;         // 2 * 1152
    unsigned* B3s2 = B1s2 + 2 * BD_STG;       // 2 * 1152

    int e = blockIdx.x / mtiles;
    int mt = blockIdx.x - e * mtiles;
    int noff = blockIdx.y * 64;
    int ctot = cnt_ ? min(cnt_[e], CAP) : mfull;
    int nrows = ctot - mt * 128;
    if (nrows <= 0) return;
    int valid = min(128, nrows);

    int tid = threadIdx.x;

    const float* ap[4]; int asoff[4];
    {
        int c4 = (tid & 7) * 4, arow0 = tid >> 3;
        #pragma unroll
        for (int i = 0; i < 4; i++) {
            int r = arow0 + i * 32;
            int rr = min(r, valid - 1);
            long grow = gather ? (long)gather[e * CAP + mt * 128 + rr] : ((long)mt * 128 + rr);
            ap[i] = A + (size_t)e * strideA + (size_t)grow * lda + c4;
            asoff[i] = r * ASTRH + (tid & 7) * 2;
        }
    }
    const float *b1p, *b3p; int bsoff;
    {
        int k2 = tid >> 4, n4 = (tid & 15) * 4;
        size_t go = (size_t)e * strideB + (size_t)(2 * k2) * ldb + noff + n4;
        b1p = B1g + go; b3p = B3g + go;
        bsoff = k2 * BSTRH_D + n4;
    }

    float c1[2][4][4], c3[2][4][4];
    #pragma unroll
    for (int a = 0; a < 2; a++)
        #pragma unroll
        for (int b = 0; b < 4; b++)
            #pragma unroll
            for (int r = 0; r < 4; r++) { c1[a][b][r] = 0.f; c3[a][b][r] = 0.f; }

    int warp = tid >> 5, lane = tid & 31;
    int wm = warp & 3, wn = warp >> 2;
    int g = lane >> 2, t4 = lane & 3;

    uint2 raA[4];
    uint4 rb1, rb3;
    auto ldg_all = [&]() {
        #pragma unroll
        for (int i = 0; i < 4; i++) {
            float4 v = *(const float4*)ap[i]; ap[i] += BKx;
            raA[i] = make_uint2(pack2(v.x, v.y), pack2(v.z, v.w));
        }
        float4 lo1 = *(const float4*)b1p, hi1 = *(const float4*)(b1p + ldb);
        b1p += (size_t)BKx * ldb;
        rb1 = make_uint4(pack2(lo1.x, hi1.x), pack2(lo1.y, hi1.y),
                         pack2(lo1.z, hi1.z), pack2(lo1.w, hi1.w));
        float4 lo3 = *(const float4*)b3p, hi3 = *(const float4*)(b3p + ldb);
        b3p += (size_t)BKx * ldb;
        rb3 = make_uint4(pack2(lo3.x, hi3.x), pack2(lo3.y, hi3.y),
                         pack2(lo3.z, hi3.z), pack2(lo3.w, hi3.w));
    };
    auto sts_all = [&](int s) {
        #pragma unroll
        for (int i = 0; i < 4; i++)
            *(uint2*)&As2[s * A_STG + asoff[i]] = raA[i];
        *(uint4*)&B1s2[s * BD_STG + bsoff] = rb1;
        *(uint4*)&B3s2[s * BD_STG + bsoff] = rb3;
    };

    int nk = K / BKx;
    ldg_all();
    for (int i = 0; i < nk; i++) {
        int s = i & 1;
        sts_all(s);
        __syncthreads();
        if (i + 1 < nk) ldg_all();
        const unsigned* as  = As2 + s * A_STG;
        const unsigned* b1s = B1s2 + s * BD_STG;
        const unsigned* b3s = B3s2 + s * BD_STG;
        #pragma unroll
        for (int kk2 = 0; kk2 < 2; kk2++) {
            int kb = kk2 * 8 + t4;
            unsigned af[2][4];
            #pragma unroll
            for (int mf = 0; mf < 2; mf++) {
                int r0 = wm * 32 + mf * 16 + g;
                af[mf][0] = as[r0 * ASTRH + kb];
                af[mf][1] = as[(r0 + 8) * ASTRH + kb];
                af[mf][2] = as[r0 * ASTRH + kb + 4];
                af[mf][3] = as[(r0 + 8) * ASTRH + kb + 4];
            }
            unsigned bf1[4][2], bf3[4][2];
            #pragma unroll
            for (int nf = 0; nf < 4; nf++) {
                int cn = wn * 32 + nf * 8 + g;
                bf1[nf][0] = b1s[kb * BSTRH_D + cn];
                bf1[nf][1] = b1s[(kb + 4) * BSTRH_D + cn];
                bf3[nf][0] = b3s[kb * BSTRH_D + cn];
                bf3[nf][1] = b3s[(kb + 4) * BSTRH_D + cn];
            }
            #pragma unroll
            for (int mf = 0; mf < 2; mf++)
                #pragma unroll
                for (int nf = 0; nf < 4; nf++) {
                    mma16(c1[mf][nf], af[mf], bf1[nf][0], bf1[nf][1]);
                    mma16(c3[mf][nf], af[mf], bf3[nf][0], bf3[nf][1]);
                }
        }
        __syncthreads();
    }

    float* outp = Out + (size_t)e * strideOut + (size_t)mt * 128 * ldo + noff;
    #pragma unroll
    for (int mf = 0; mf < 2; mf++)
        #pragma unroll
        for (int nf = 0; nf < 4; nf++) {
            int r0 = wm * 32 + mf * 16 + g;
            int cc = wn * 32 + nf * 8 + t4 * 2;
            #pragma unroll
            for (int h = 0; h < 2; h++) {
                int r = r0 + h * 8;
                if (r < valid) {
                    float v1a = c1[mf][nf][h * 2 + 0], v3a = c3[mf][nf][h * 2 + 0];
                    float v1b = c1[mf][nf][h * 2 + 1], v3b = c3[mf][nf][h * 2 + 1];
                    float ga = (v1a / (1.f + expf(-v1a))) * v3a;
                    float gb = (v1b / (1.f + expf(-v1b))) * v3b;
                    *(float2*)(outp + (size_t)r * ldo + cc) = make_float2(ga, gb);
                }
            }
        }
}

// ---------------- single GEMM fp16 (C = A @ B) ----------------
// 256 threads, 8 warps (4m x 2n), block tile 128x128, warp tile 32x64.
__global__ void __launch_bounds__(256, 2)
single_gemm(const float* __restrict__ A, int lda, size_t strideA,
            const int* __restrict__ cnt_, int mfull, int mtiles,
            const float* __restrict__ Bg, int ldb, size_t strideB,
            float* __restrict__ Out, int ldo, size_t strideOut, int K) {
    extern __shared__ unsigned smu[];
    unsigned* As2 = smu;                  // 2 * 2560
    unsigned* Bs2 = smu + 2 * A_STG;      // 2 * 2176

    int e = blockIdx.x / mtiles;
    int mt = blockIdx.x - e * mtiles;
    int noff = blockIdx.y * 128;
    int ctot = cnt_ ? min(cnt_[e], CAP) : mfull;
    int nrows = ctot - mt * 128;
    if (nrows <= 0) return;
    int valid = min(128, nrows);

    int tid = threadIdx.x;

    const float* ap[4]; int asoff[4];
    {
        int c4 = (tid & 7) * 4, arow0 = tid >> 3;
        #pragma unroll
        for (int i = 0; i < 4; i++) {
            int r = arow0 + i * 32;
            int rr = min(r, valid - 1);
            ap[i] = A + (size_t)e * strideA + ((size_t)mt * 128 + rr) * lda + c4;
            asoff[i] = r * ASTRH + (tid & 7) * 2;
        }
    }
    const float* bp[2]; int bsoff[2];
    #pragma unroll
    for (int j = 0; j < 2; j++) {
        int slot = tid + j * 256;
        int k2 = slot >> 5, n4 = (slot & 31) * 4;
        bp[j] = Bg + (size_t)e * strideB + (size_t)(2 * k2) * ldb + noff + n4;
        bsoff[j] = k2 * BSTRH_S + n4;
    }

    float c[2][8][4];
    #pragma unroll
    for (int a = 0; a < 2; a++)
        #pragma unroll
        for (int b = 0; b < 8; b++)
            #pragma unroll
            for (int r = 0; r < 4; r++) c[a][b][r] = 0.f;

    int warp = tid >> 5, lane = tid & 31;
    int wm = warp & 3, wn = warp >> 2;
    int g = lane >> 2, t4 = lane & 3;

    uint2 raA[4];
    uint4 rbS[2];
    auto ldg_all = [&]() {
        #pragma unroll
        for (int i = 0; i < 4; i++) {
            float4 v = *(const float4*)ap[i]; ap[i] += BKx;
            raA[i] = make_uint2(pack2(v.x, v.y), pack2(v.z, v.w));
        }
        #pragma unroll
        for (int j = 0; j < 2; j++) {
            float4 lo = *(const float4*)bp[j], hi = *(const float4*)(bp[j] + ldb);
            bp[j] += (size_t)BKx * ldb;
            rbS[j] = make_uint4(pack2(lo.x, hi.x), pack2(lo.y, hi.y),
                                pack2(lo.z, hi.z), pack2(lo.w, hi.w));
        }
    };
    auto sts_all = [&](int s) {
        #pragma unroll
        for (int i = 0; i < 4; i++)
            *(uint2*)&As2[s * A_STG + asoff[i]] = raA[i];
        #pragma unroll
        for (int j = 0; j < 2; j++)
            *(uint4*)&Bs2[s * BS_STG + bsoff[j]] = rbS[j];
    };

    int nk = K / BKx;
    ldg_all();
    for (int i = 0; i < nk; i++) {
        int s = i & 1;
        sts_all(s);
        __syncthreads();
        if (i + 1 < nk) ldg_all();
        const unsigned* as = As2 + s * A_STG;
        const unsigned* bs = Bs2 + s * BS_STG;
        #pragma unroll
        for (int kk2 = 0; kk2 < 2; kk2++) {
            int kb = kk2 * 8 + t4;
            unsigned af[2][4];
            #pragma unroll
            for (int mf = 0; mf < 2; mf++) {
                int r0 = wm * 32 + mf * 16 + g;
                af[mf][0] = as[r0 * ASTRH + kb];
                af[mf][1] = as[(r0 + 8) * ASTRH + kb];
                af[mf][2] = as[r0 * ASTRH + kb + 4];
                af[mf][3] = as[(r0 + 8) * ASTRH + kb + 4];
            }
            unsigned bf[8][2];
            #pragma unroll
            for (int nf = 0; nf < 8; nf++) {
                int cn = wn * 64 + nf * 8 + g;
                bf[nf][0] = bs[kb * BSTRH_S + cn];
                bf[nf][1] = bs[(kb + 4) * BSTRH_S + cn];
            }
            #pragma unroll
            for (int mf = 0; mf < 2; mf++)
                #pragma unroll
                for (int nf = 0; nf < 8; nf++)
                    mma16(c[mf][nf], af[mf], bf[nf][0], bf[nf][1]);
        }
        __syncthreads();
    }

    float* outp = Out + (size_t)e * strideOut + (size_t)mt * 128 * ldo + noff;
    #pragma unroll
    for (int mf = 0; mf < 2; mf++)
        #pragma unroll
        for (int nf = 0; nf < 8; nf++) {
            int r0 = wm * 32 + mf * 16 + g;
            int cc = wn * 64 + nf * 8 + t4 * 2;
            #pragma unroll
            for (int h = 0; h < 2; h++) {
                int r = r0 + h * 8;
                if (r < valid)
                    *(float2*)(outp + (size_t)r * ldo + cc) =
                        make_float2(c[mf][nf][h * 2 + 0], c[mf][nf][h * 2 + 1]);
            }
        }
}

// ---------------- combine: routed + sigmoid-gated shared ----------------
__global__ void combine_kernel(float* __restrict__ out) {
    int t = blockIdx.x;
    __shared__ int rows[TOPK];
    __shared__ float ws[TOPK];
    if (threadIdx.x < TOPK) {
        int k = threadIdx.x;
        int ee = d_topk_idx[t * TOPK + k];
        int p  = d_pos[t * TOPK + k];
        rows[k] = (p < CAP) ? (ee * CAP + p) : -1;
        ws[k] = d_topk_w[t * TOPK + k];
    }
    __syncthreads();
    float sg = 1.f / (1.f + expf(-d_sgate[t]));
    #pragma unroll
    for (int j = 0; j < 2; j++) {
        int h = threadIdx.x * 4 + j * 1024;
        float4 acc = *(const float4*)(d_s2 + (size_t)t * H_DIM + h);
        acc.x *= sg; acc.y *= sg; acc.z *= sg; acc.w *= sg;
        #pragma unroll
        for (int k = 0; k < TOPK; k++) {
            int r = rows[k];
            if (r >= 0) {
                float w = ws[k];
                float4 y = *(const float4*)(d_yb + (size_t)r * H_DIM + h);
                acc.x += w * y.x; acc.y += w * y.y; acc.z += w * y.z; acc.w += w * y.w;
            }
        }
        *(float4*)(out + (size_t)t * H_DIM + h) = acc;
    }
}

// ---------------- launch ----------------
extern "C" void kernel_launch(void* const* d_in, const int* in_sizes, int n_in,
                              void* d_out, int out_size) {
    (void)in_sizes; (void)n_in; (void)out_size;
    const float* x   = (const float*)d_in[0];
    const float* gw  = (const float*)d_in[1];
    const float* w1  = (const float*)d_in[2];
    const float* w3  = (const float*)d_in[3];
    const float* w2  = (const float*)d_in[4];
    const float* ws1 = (const float*)d_in[5];
    const float* ws3 = (const float*)d_in[6];
    const float* ws2 = (const float*)d_in[7];
    const float* wsg = (const float*)d_in[8];
    float* out = (float*)d_out;

    static cudaStream_t sB = nullptr, sC = nullptr;
    static cudaEvent_t evFork = nullptr, evJoin = nullptr, evDisp = nullptr, evC = nullptr;
    if (sB == nullptr) {
        cudaStreamCreateWithFlags(&sB, cudaStreamNonBlocking);
        cudaStreamCreateWithFlags(&sC, cudaStreamNonBlocking);
        cudaEventCreateWithFlags(&evFork, cudaEventDisableTiming);
        cudaEventCreateWithFlags(&evJoin, cudaEventDisableTiming);
        cudaEventCreateWithFlags(&evDisp, cudaEventDisableTiming);
        cudaEventCreateWithFlags(&evC, cudaEventDisableTiming);
    }

    cudaFuncSetAttribute(dual_gemm_silu, cudaFuncAttributeMaxDynamicSharedMemorySize, SMEM_DUAL);
    cudaFuncSetAttribute(single_gemm,    cudaFuncAttributeMaxDynamicSharedMemorySize, SMEM_SINGLE);

    float *gbuf, *yb, *s1, *s2;
    int *cnt, *toklist;
    cudaGetSymbolAddress((void**)&gbuf, d_gbuf);
    cudaGetSymbolAddress((void**)&yb, d_yb);
    cudaGetSymbolAddress((void**)&s1, d_s1);
    cudaGetSymbolAddress((void**)&s2, d_s2);
    cudaGetSymbolAddress((void**)&cnt, d_cnt);
    cudaGetSymbolAddress((void**)&toklist, d_toklist);

    const int EH = E_NUM / 2;   // 32 experts per half
    const size_t strB1 = (size_t)H_DIM * I_DIM;
    const size_t strO1 = (size_t)CAP * I_DIM;
    const size_t strA2 = (size_t)CAP * I_DIM;
    const size_t strB2 = (size_t)I_DIM * H_DIM;
    const size_t strO2 = (size_t)CAP * H_DIM;

    // fork: shared-expert chain is independent of router/dispatch/experts
    cudaEventRecord(evFork, 0);
    cudaStreamWaitEvent(sB, evFork, 0);

    // ---- stream B: shared expert chain ----
    dual_gemm_silu<<<dim3(8, IS_DIM / 64), 256, SMEM_DUAL, sB>>>(
        x, H_DIM, 0, nullptr, nullptr, T_TOK, 8,
        ws1, ws3, IS_DIM, 0,
        s1, IS_DIM, 0, H_DIM);
    single_gemm<<<dim3(8, H_DIM / 128), 256, SMEM_SINGLE, sB>>>(
        s1, IS_DIM, 0, nullptr, T_TOK, 8,
        ws2, H_DIM, 0,
        s2, H_DIM, 0, IS_DIM);
    cudaEventRecord(evJoin, sB);

    // ---- default stream: router + dispatch, then experts 0..31 ----
    router_kernel<<<T_TOK / 8, 256>>>(x, gw, wsg);
    dispatch_kernel<<<8, 1024>>>();
    cudaEventRecord(evDisp, 0);
    cudaStreamWaitEvent(sC, evDisp, 0);

    // half 1 (experts 0..31) on default stream
    dual_gemm_silu<<<dim3(EH * 2, I_DIM / 64), 256, SMEM_DUAL>>>(
        x, H_DIM, 0, toklist, cnt, 0, 2,
        w1, w3, I_DIM, strB1,
        gbuf, I_DIM, strO1, H_DIM);
    single_gemm<<<dim3(EH * 2, H_DIM / 128), 256, SMEM_SINGLE>>>(
        gbuf, I_DIM, strA2, cnt, 0, 2,
        w2, H_DIM, strB2,
        yb, H_DIM, strO2, I_DIM);

    // half 2 (experts 32..63) on stream C
    dual_gemm_silu<<<dim3(EH * 2, I_DIM / 64), 256, SMEM_DUAL, sC>>>(
        x, H_DIM, 0, toklist + EH * CAP, cnt + EH, 0, 2,
        w1 + EH * strB1, w3 + EH * strB1, I_DIM, strB1,
        gbuf + EH * strO1, I_DIM, strO1, H_DIM);
    single_gemm<<<dim3(EH * 2, H_DIM / 128), 256, SMEM_SINGLE, sC>>>(
        gbuf + EH * strA2, I_DIM, strA2, cnt + EH, 0, 2,
        w2 + EH * strB2, H_DIM, strB2,
        yb + EH * strO2, H_DIM, strO2, I_DIM);
    cudaEventRecord(evC, sC);

    // join: combine needs both expert halves and the shared chain
    cudaStreamWaitEvent(0, evJoin, 0);
    cudaStreamWaitEvent(0, evC, 0);
    combine_kernel<<<T_TOK, 256>>>(out);
}